// round 5
// baseline (speedup 1.0000x reference)
#include <cuda_runtime.h>
#include <math.h>

// Problem constants
#define NTOK 4096
#define NH   16
#define HD   64
#define EMB  1024

// Scratch (no allocations allowed -> __device__ globals). 64 MB total.
__device__ __align__(128) float g_Q[NH * NTOK * HD];   // [h][n][d], pre-scaled by 1/sqrt(64)
__device__ __align__(128) float g_K[NH * NTOK * HD];   // [h][n][d]
__device__ __align__(128) float g_V[NH * NTOK * HD];   // [h][n][d]
__device__ __align__(128) float g_O[NTOK * EMB];       // [n][h*64+d]

// ---------------------------------------------------------------------------
// Classic 128x128x8 fp32 SGEMM, C = A * B^T  (both A and B row-major, K=1024
// contiguous). 256 threads, 8x8 micro-tile per thread.
// MODE 0: A = x [4096,1024], B = qkv_w [3072,1024]; scatter to g_Q/g_K/g_V,
//         Q scaled by 0.125.
// MODE 1: A = g_O [4096,1024], B = out_w [1024,1024]; C = y + bias.
// ---------------------------------------------------------------------------
template <int MODE>
__global__ void __launch_bounds__(256)
sgemm_nt(const float* __restrict__ A, const float* __restrict__ B,
         const float* __restrict__ bias, float* __restrict__ C)
{
    __shared__ float As[8][128];
    __shared__ float Bs[8][128];

    const int t  = threadIdx.x;
    const int bm = blockIdx.y;
    const int bn = blockIdx.x;
    const int tm = (t >> 4) << 3;   // 0..120 step 8
    const int tn = (t & 15) << 3;   // 0..120 step 8
    const int lr = t >> 1;          // 0..127 (tile row to load)
    const int lk = (t & 1) << 2;    // 0 or 4 (k sub-chunk)

    const float* Abase = (MODE == 1) ? (const float*)g_O : A;
    const float* Ap = Abase + (size_t)(bm * 128 + lr) * 1024 + lk;
    const float* Bp = B     + (size_t)(bn * 128 + lr) * 1024 + lk;

    float acc[8][8];
#pragma unroll
    for (int i = 0; i < 8; i++)
#pragma unroll
        for (int j = 0; j < 8; j++) acc[i][j] = 0.f;

    for (int k0 = 0; k0 < 1024; k0 += 8) {
        float4 a4 = *(const float4*)(Ap + k0);
        float4 b4 = *(const float4*)(Bp + k0);
        As[lk + 0][lr] = a4.x; As[lk + 1][lr] = a4.y;
        As[lk + 2][lr] = a4.z; As[lk + 3][lr] = a4.w;
        Bs[lk + 0][lr] = b4.x; Bs[lk + 1][lr] = b4.y;
        Bs[lk + 2][lr] = b4.z; Bs[lk + 3][lr] = b4.w;
        __syncthreads();
#pragma unroll
        for (int kk = 0; kk < 8; kk++) {
            float ar[8], br[8];
            *(float4*)(ar)     = *(const float4*)(&As[kk][tm]);
            *(float4*)(ar + 4) = *(const float4*)(&As[kk][tm + 4]);
            *(float4*)(br)     = *(const float4*)(&Bs[kk][tn]);
            *(float4*)(br + 4) = *(const float4*)(&Bs[kk][tn + 4]);
#pragma unroll
            for (int i = 0; i < 8; i++)
#pragma unroll
                for (int j = 0; j < 8; j++)
                    acc[i][j] = fmaf(ar[i], br[j], acc[i][j]);
        }
        __syncthreads();
    }

    if (MODE == 0) {
        // bn in [0,24): part boundaries at bn multiples of 8 (1024 cols)
        const int part = bn >> 3;                // 0=Q, 1=K, 2=V
        const float scale = (part == 0) ? 0.125f : 1.0f;  // 1/sqrt(64) on Q
        float* dst = (part == 0) ? g_Q : ((part == 1) ? g_K : g_V);
#pragma unroll
        for (int i = 0; i < 8; i++) {
            const int row = bm * 128 + tm + i;
#pragma unroll
            for (int j = 0; j < 8; j++) {
                const int e   = bn * 128 + tn + j;
                const int rem = e & 1023;
                const int h   = rem >> 6;
                const int d   = rem & 63;
                dst[((size_t)h * NTOK + row) * HD + d] = acc[i][j] * scale;
            }
        }
    } else {
        float bv[8];
#pragma unroll
        for (int j = 0; j < 8; j++) bv[j] = bias[bn * 128 + tn + j];
#pragma unroll
        for (int i = 0; i < 8; i++) {
            const int row = bm * 128 + tm + i;
            float* cp = C + (size_t)row * 1024 + bn * 128 + tn;
            float4 o0 = make_float4(acc[i][0] + bv[0], acc[i][1] + bv[1],
                                    acc[i][2] + bv[2], acc[i][3] + bv[3]);
            float4 o1 = make_float4(acc[i][4] + bv[4], acc[i][5] + bv[5],
                                    acc[i][6] + bv[6], acc[i][7] + bv[7]);
            *(float4*)cp       = o0;
            *(float4*)(cp + 4) = o1;
        }
    }
}

// ---------------------------------------------------------------------------
// Flash attention (fp32, online softmax). One CTA = 64 queries of one head.
// 256 threads = 16 row-groups x 16 col-lanes. Thread owns S/O rows 4*tr..+3
// and strided columns {tc, tc+16, tc+32, tc+48} (lane-consecutive SMEM access).
// Row-group (16 lanes) lives inside one half-warp -> softmax via SHFL.XOR 1/2/4/8.
// SMEM: Q,K,V,P tiles, 64 rows x (64+4 pad) floats each = 69632 B (dynamic).
// ---------------------------------------------------------------------------
#define LDSZ 68
#define ATTN_SMEM (4 * 64 * LDSZ * (int)sizeof(float))

__global__ void __launch_bounds__(256)
attn_kernel()
{
    extern __shared__ float sm[];
    float* Qs = sm;
    float* Ks = sm + 64 * LDSZ;
    float* Vs = sm + 2 * 64 * LDSZ;
    float* Ps = sm + 3 * 64 * LDSZ;

    const int t  = threadIdx.x;
    const int qb = blockIdx.x;   // query block (64 rows)
    const int h  = blockIdx.y;   // head
    const int tr = t >> 4;       // 0..15 row group
    const int tc = t & 15;       // 0..15 col lane

    const float* Qg = g_Q + ((size_t)h * NTOK + qb * 64) * HD;
    const float* Kg = g_K + (size_t)h * NTOK * HD;
    const float* Vg = g_V + (size_t)h * NTOK * HD;

    // Load Q tile once
    for (int idx = t; idx < 1024; idx += 256) {
        int r = idx >> 4, c = (idx & 15) << 2;
        *(float4*)(Qs + r * LDSZ + c) = *(const float4*)(Qg + r * 64 + c);
    }

    float o[4][4];
    float m[4], l[4];
#pragma unroll
    for (int i = 0; i < 4; i++) {
        m[i] = -1e30f; l[i] = 0.f;
#pragma unroll
        for (int j = 0; j < 4; j++) o[i][j] = 0.f;
    }
    __syncthreads();

    for (int kb = 0; kb < NTOK / 64; kb++) {
        const float* Kt = Kg + (size_t)kb * 64 * HD;
        const float* Vt = Vg + (size_t)kb * 64 * HD;
        for (int idx = t; idx < 1024; idx += 256) {
            int r = idx >> 4, c = (idx & 15) << 2;
            *(float4*)(Ks + r * LDSZ + c) = *(const float4*)(Kt + r * 64 + c);
            *(float4*)(Vs + r * LDSZ + c) = *(const float4*)(Vt + r * 64 + c);
        }
        __syncthreads();

        // S = Q * K^T  (Q already scaled by 1/sqrt(D))
        float s[4][4];
#pragma unroll
        for (int i = 0; i < 4; i++)
#pragma unroll
            for (int j = 0; j < 4; j++) s[i][j] = 0.f;

#pragma unroll 4
        for (int d = 0; d < 64; d += 4) {
            float4 q[4], k[4];
#pragma unroll
            for (int i = 0; i < 4; i++)
                q[i] = *(const float4*)(Qs + (tr * 4 + i) * LDSZ + d);
#pragma unroll
            for (int j = 0; j < 4; j++)
                k[j] = *(const float4*)(Ks + (tc + 16 * j) * LDSZ + d);
#pragma unroll
            for (int i = 0; i < 4; i++)
#pragma unroll
                for (int j = 0; j < 4; j++) {
                    s[i][j] = fmaf(q[i].x, k[j].x, s[i][j]);
                    s[i][j] = fmaf(q[i].y, k[j].y, s[i][j]);
                    s[i][j] = fmaf(q[i].z, k[j].z, s[i][j]);
                    s[i][j] = fmaf(q[i].w, k[j].w, s[i][j]);
                }
        }

        // Online softmax (row reductions across the 16-lane row group)
#pragma unroll
        for (int i = 0; i < 4; i++) {
            float mx = fmaxf(fmaxf(s[i][0], s[i][1]), fmaxf(s[i][2], s[i][3]));
            mx = fmaxf(mx, __shfl_xor_sync(0xffffffffu, mx, 1));
            mx = fmaxf(mx, __shfl_xor_sync(0xffffffffu, mx, 2));
            mx = fmaxf(mx, __shfl_xor_sync(0xffffffffu, mx, 4));
            mx = fmaxf(mx, __shfl_xor_sync(0xffffffffu, mx, 8));
            const float mnew  = fmaxf(m[i], mx);
            const float alpha = __expf(m[i] - mnew);
            float sum = 0.f;
#pragma unroll
            for (int j = 0; j < 4; j++) {
                float p = __expf(s[i][j] - mnew);
                s[i][j] = p;
                sum += p;
            }
            sum += __shfl_xor_sync(0xffffffffu, sum, 1);
            sum += __shfl_xor_sync(0xffffffffu, sum, 2);
            sum += __shfl_xor_sync(0xffffffffu, sum, 4);
            sum += __shfl_xor_sync(0xffffffffu, sum, 8);
            l[i] = l[i] * alpha + sum;
            m[i] = mnew;
#pragma unroll
            for (int j = 0; j < 4; j++) {
                o[i][j] *= alpha;
                Ps[(tr * 4 + i) * LDSZ + tc + 16 * j] = s[i][j];
            }
        }
        // P rows are produced and consumed by the same half-warp (row group)
        __syncwarp();

        // O += P * V
#pragma unroll 4
        for (int k4 = 0; k4 < 64; k4 += 4) {
            float4 p[4];
#pragma unroll
            for (int i = 0; i < 4; i++)
                p[i] = *(const float4*)(Ps + (tr * 4 + i) * LDSZ + k4);
            float v[4][4];
#pragma unroll
            for (int kk = 0; kk < 4; kk++)
#pragma unroll
                for (int j = 0; j < 4; j++)
                    v[kk][j] = Vs[(k4 + kk) * LDSZ + tc + 16 * j];
#pragma unroll
            for (int i = 0; i < 4; i++)
#pragma unroll
                for (int j = 0; j < 4; j++) {
                    o[i][j] = fmaf(p[i].x, v[0][j], o[i][j]);
                    o[i][j] = fmaf(p[i].y, v[1][j], o[i][j]);
                    o[i][j] = fmaf(p[i].z, v[2][j], o[i][j]);
                    o[i][j] = fmaf(p[i].w, v[3][j], o[i][j]);
                }
        }
        __syncthreads();  // everyone done with Ks/Vs before next tile load
    }

    // Normalize and write O in [n][h*64+d] layout for the output projection
#pragma unroll
    for (int i = 0; i < 4; i++) {
        const float inv = 1.f / l[i];
        const int row = qb * 64 + tr * 4 + i;
#pragma unroll
        for (int j = 0; j < 4; j++)
            g_O[(size_t)row * EMB + h * HD + tc + 16 * j] = o[i][j] * inv;
    }
}

// ---------------------------------------------------------------------------
extern "C" void kernel_launch(void* const* d_in, const int* in_sizes, int n_in,
                              void* d_out, int out_size)
{
    (void)in_sizes; (void)n_in; (void)out_size;
    const float* x     = (const float*)d_in[0];   // [1,4096,1024]
    const float* qkv_w = (const float*)d_in[1];   // [3072,1024]
    const float* out_w = (const float*)d_in[2];   // [1024,1024]
    const float* out_b = (const float*)d_in[3];   // [1024]
    float* y = (float*)d_out;                     // [1,4096,1024]

    // 1) QKV projection: scatter into g_Q/g_K/g_V (Q scaled by 1/8)
    sgemm_nt<0><<<dim3(24, 32), 256>>>(x, qkv_w, nullptr, nullptr);

    // 2) Flash attention per head
    cudaFuncSetAttribute(attn_kernel,
                         cudaFuncAttributeMaxDynamicSharedMemorySize, ATTN_SMEM);
    attn_kernel<<<dim3(NTOK / 64, NH), 256, ATTN_SMEM>>>();

    // 3) Output projection + bias
    sgemm_nt<1><<<dim3(8, 32), 256>>>(nullptr, out_w, out_b, y);
}

// round 8
// speedup vs baseline: 1.9374x; 1.9374x over previous
#include <cuda_runtime.h>
#include <math.h>
#include <stdint.h>

// ============================================================================
// Problem constants
// ============================================================================
#define NTOK 4096
#define NH   16
#define HD   64
#define EMB  1024

// Scratch (__device__ globals; no allocations allowed)
__device__ __align__(128) float g_Q[NH * NTOK * HD];   // [h][n][d], *0.125, tf32-rounded
__device__ __align__(128) float g_K[NH * NTOK * HD];   // tf32-rounded
__device__ __align__(128) float g_V[NH * NTOK * HD];   // tf32-rounded
__device__ __align__(128) float g_O[NTOK * EMB];       // [n][h*64+d], tf32-rounded

// ============================================================================
// Helpers
// ============================================================================
__device__ __forceinline__ float rna_tf32(float x) {
    float y; asm("cvt.rna.tf32.f32 %0, %1;" : "=f"(y) : "f"(x)); return y;
}
__device__ __forceinline__ uint32_t fau(float x) { return __float_as_uint(x); }

// D += A*B, m16n8k8 tf32 (A row-major 16x8, B col-major 8x8, f32 accum)
__device__ __forceinline__ void mma8(float* d, const uint32_t* a, uint32_t b0, uint32_t b1) {
    asm volatile(
        "mma.sync.aligned.m16n8k8.row.col.f32.tf32.tf32.f32 "
        "{%0,%1,%2,%3}, {%4,%5,%6,%7}, {%8,%9}, {%0,%1,%2,%3};"
        : "+f"(d[0]), "+f"(d[1]), "+f"(d[2]), "+f"(d[3])
        : "r"(a[0]), "r"(a[1]), "r"(a[2]), "r"(a[3]), "r"(b0), "r"(b1));
}

// ============================================================================
// tf32 mma.sync GEMM: C[128x128 tile] = A[Mx1024] * B[Nx1024]^T
// 256 threads = 8 warps as 2(m)x4(n); warp tile 64x32; K-tile 32, 2-stage smem.
// Operands rna-rounded to tf32 at SMEM store.
// MODE 0: A=x, B=qkv_w -> scatter rna(Q*0.125)/rna(K)/rna(V)
// MODE 1: A=g_O, B=out_w -> C = y + bias (fp32)
// ============================================================================
#define GPAD 36
#define GEMM_SMEM (4 * 128 * GPAD * (int)sizeof(float))   // 2 stages x (A+B)

template <int MODE>
__global__ void __launch_bounds__(256)
tc_gemm(const float* __restrict__ A, const float* __restrict__ B,
        const float* __restrict__ bias, float* __restrict__ C)
{
    extern __shared__ float gs[];
    float* sA[2] = { gs,                gs + 2 * 128 * GPAD };
    float* sB[2] = { gs + 128 * GPAD,   gs + 3 * 128 * GPAD };

    const int t    = threadIdx.x;
    const int wid  = t >> 5;
    const int lane = t & 31;
    const int g    = lane >> 2;      // group id (0..7)
    const int tg   = lane & 3;       // thread in group
    const int bm   = blockIdx.y, bn = blockIdx.x;
    const int wm   = (wid & 1) * 64;
    const int wn   = (wid >> 1) * 32;

    // global load mapping: warp covers 4 rows x 32 floats, 4 passes
    const int lrow0 = wid * 4 + (lane >> 3);   // 0..31
    const int lcol  = (lane & 7) * 4;          // 0..28

    const float* Ap = A + (size_t)(bm * 128 + lrow0) * 1024 + lcol;
    const float* Bp = B + (size_t)(bn * 128 + lrow0) * 1024 + lcol;

    float d[4][4][4];
#pragma unroll
    for (int mt = 0; mt < 4; mt++)
#pragma unroll
        for (int nt = 0; nt < 4; nt++)
#pragma unroll
            for (int r = 0; r < 4; r++) d[mt][nt][r] = 0.f;

    float4 ra[4], rb[4];
    auto ldg = [&](int kt) {
#pragma unroll
        for (int i = 0; i < 4; i++) {
            ra[i] = *(const float4*)(Ap + (size_t)i * 32 * 1024 + kt * 32);
            rb[i] = *(const float4*)(Bp + (size_t)i * 32 * 1024 + kt * 32);
        }
    };
    auto sts = [&](int st) {
#pragma unroll
        for (int i = 0; i < 4; i++) {
            float4 a = ra[i], b = rb[i];
            a.x = rna_tf32(a.x); a.y = rna_tf32(a.y); a.z = rna_tf32(a.z); a.w = rna_tf32(a.w);
            b.x = rna_tf32(b.x); b.y = rna_tf32(b.y); b.z = rna_tf32(b.z); b.w = rna_tf32(b.w);
            *(float4*)(sA[st] + (lrow0 + i * 32) * GPAD + lcol) = a;
            *(float4*)(sB[st] + (lrow0 + i * 32) * GPAD + lcol) = b;
        }
    };

    ldg(0);
    sts(0);
    __syncthreads();

    for (int kt = 0; kt < 32; kt++) {
        const int cur = kt & 1;
        if (kt + 1 < 32) ldg(kt + 1);

        const float* cA = sA[cur];
        const float* cB = sB[cur];
#pragma unroll
        for (int ks = 0; ks < 4; ks++) {
            uint32_t a[4][4], b[4][2];
#pragma unroll
            for (int mt = 0; mt < 4; mt++) {
                const int r = wm + mt * 16 + g;
                a[mt][0] = fau(cA[r * GPAD + ks * 8 + tg]);
                a[mt][1] = fau(cA[(r + 8) * GPAD + ks * 8 + tg]);
                a[mt][2] = fau(cA[r * GPAD + ks * 8 + tg + 4]);
                a[mt][3] = fau(cA[(r + 8) * GPAD + ks * 8 + tg + 4]);
            }
#pragma unroll
            for (int nt = 0; nt < 4; nt++) {
                const int r = wn + nt * 8 + g;
                b[nt][0] = fau(cB[r * GPAD + ks * 8 + tg]);
                b[nt][1] = fau(cB[r * GPAD + ks * 8 + tg + 4]);
            }
#pragma unroll
            for (int mt = 0; mt < 4; mt++)
#pragma unroll
                for (int nt = 0; nt < 4; nt++)
                    mma8(d[mt][nt], a[mt], b[nt][0], b[nt][1]);
        }
        if (kt + 1 < 32) sts(cur ^ 1);
        __syncthreads();
    }

    // Epilogue. C fragment (m16n8): c0=(g,2tg) c1=(g,2tg+1) c2=(g+8,2tg) c3=(g+8,2tg+1)
    if (MODE == 0) {
        const int part = bn >> 3;                      // 0=Q 1=K 2=V
        const float scale = (part == 0) ? 0.125f : 1.0f;
        float* dst = (part == 0) ? g_Q : ((part == 1) ? g_K : g_V);
#pragma unroll
        for (int mt = 0; mt < 4; mt++) {
            const int row = bm * 128 + wm + mt * 16 + g;
#pragma unroll
            for (int nt = 0; nt < 4; nt++) {
                const int e  = bn * 128 + wn + nt * 8 + 2 * tg;
                const int h  = (e & 1023) >> 6;
                const int d0 = e & 63;
                float2 v0 = make_float2(rna_tf32(d[mt][nt][0] * scale),
                                        rna_tf32(d[mt][nt][1] * scale));
                float2 v1 = make_float2(rna_tf32(d[mt][nt][2] * scale),
                                        rna_tf32(d[mt][nt][3] * scale));
                *(float2*)&dst[((size_t)h * NTOK + row) * HD + d0]     = v0;
                *(float2*)&dst[((size_t)h * NTOK + row + 8) * HD + d0] = v1;
            }
        }
    } else {
#pragma unroll
        for (int mt = 0; mt < 4; mt++) {
            const int row = bm * 128 + wm + mt * 16 + g;
#pragma unroll
            for (int nt = 0; nt < 4; nt++) {
                const int e = bn * 128 + wn + nt * 8 + 2 * tg;
                const float b0 = bias[e], b1 = bias[e + 1];
                float2 v0 = make_float2(d[mt][nt][0] + b0, d[mt][nt][1] + b1);
                float2 v1 = make_float2(d[mt][nt][2] + b0, d[mt][nt][3] + b1);
                *(float2*)&C[(size_t)row * EMB + e]       = v0;
                *(float2*)&C[(size_t)(row + 8) * EMB + e] = v1;
            }
        }
    }
}

// ============================================================================
// Flash attention on tf32 mma.sync. CTA = 64 queries x 1 head, 128 threads
// (4 warps; warp w owns query rows 16w..16w+15). Q fragments held in regs.
// S = Q*K^T and O += P*V via m16n8k8; online softmax on C-fragment registers.
// ============================================================================
#define LDSZ 68
#define ATTN_SMEM (4 * 64 * LDSZ * (int)sizeof(float))

__global__ void __launch_bounds__(128)
attn_kernel()
{
    extern __shared__ float sm[];
    float* Qs = sm;
    float* Ks = sm + 64 * LDSZ;
    float* Vs = sm + 2 * 64 * LDSZ;
    float* Ps = sm + 3 * 64 * LDSZ;

    const int t    = threadIdx.x;
    const int w    = t >> 5;
    const int lane = t & 31;
    const int g    = lane >> 2;
    const int tg   = lane & 3;
    const int qb   = blockIdx.x;
    const int h    = blockIdx.y;
    const int qr   = 16 * w + g;          // query row (lower of pair) in tile

    const float* Qg = g_Q + ((size_t)h * NTOK + qb * 64) * HD;
    const float* Kg = g_K + (size_t)h * NTOK * HD;
    const float* Vg = g_V + (size_t)h * NTOK * HD;

    // Load Q tile
    for (int idx = t; idx < 1024; idx += 128) {
        int r = idx >> 4, c = (idx & 15) << 2;
        *(float4*)(Qs + r * LDSZ + c) = *(const float4*)(Qg + r * 64 + c);
    }
    __syncthreads();

    // Q fragments in registers: q[ks][0..3], ks over d (8 chunks of 8)
    uint32_t q[8][4];
#pragma unroll
    for (int ks = 0; ks < 8; ks++) {
        q[ks][0] = fau(Qs[qr * LDSZ + ks * 8 + tg]);
        q[ks][1] = fau(Qs[(qr + 8) * LDSZ + ks * 8 + tg]);
        q[ks][2] = fau(Qs[qr * LDSZ + ks * 8 + tg + 4]);
        q[ks][3] = fau(Qs[(qr + 8) * LDSZ + ks * 8 + tg + 4]);
    }

    float o[8][4];
#pragma unroll
    for (int nt = 0; nt < 8; nt++)
#pragma unroll
        for (int r = 0; r < 4; r++) o[nt][r] = 0.f;
    float mr0 = -1e30f, mr1 = -1e30f, lr0 = 0.f, lr1 = 0.f;

    for (int kb = 0; kb < NTOK / 64; kb++) {
        const float* Kt = Kg + (size_t)kb * 64 * HD;
        const float* Vt = Vg + (size_t)kb * 64 * HD;
        for (int idx = t; idx < 1024; idx += 128) {
            int r = idx >> 4, c = (idx & 15) << 2;
            *(float4*)(Ks + r * LDSZ + c) = *(const float4*)(Kt + r * 64 + c);
            *(float4*)(Vs + r * LDSZ + c) = *(const float4*)(Vt + r * 64 + c);
        }
        __syncthreads();

        // ---- S = Q * K^T  (m=16 queries, n=8 keys per tile, k=d) ----
        float s[8][4];
#pragma unroll
        for (int nt = 0; nt < 8; nt++)
#pragma unroll
            for (int r = 0; r < 4; r++) s[nt][r] = 0.f;

#pragma unroll
        for (int ks = 0; ks < 8; ks++) {
#pragma unroll
            for (int nt = 0; nt < 8; nt++) {
                const float* kp = Ks + (nt * 8 + g) * LDSZ + ks * 8 + tg;
                mma8(s[nt], q[ks], fau(kp[0]), fau(kp[4]));
            }
        }

        // ---- online softmax (rows qr and qr+8) ----
        float mx0 = -1e30f, mx1 = -1e30f;
#pragma unroll
        for (int nt = 0; nt < 8; nt++) {
            mx0 = fmaxf(mx0, fmaxf(s[nt][0], s[nt][1]));
            mx1 = fmaxf(mx1, fmaxf(s[nt][2], s[nt][3]));
        }
        mx0 = fmaxf(mx0, __shfl_xor_sync(0xffffffffu, mx0, 1));
        mx0 = fmaxf(mx0, __shfl_xor_sync(0xffffffffu, mx0, 2));
        mx1 = fmaxf(mx1, __shfl_xor_sync(0xffffffffu, mx1, 1));
        mx1 = fmaxf(mx1, __shfl_xor_sync(0xffffffffu, mx1, 2));

        const float mn0 = fmaxf(mr0, mx0);
        const float mn1 = fmaxf(mr1, mx1);
        const float a0  = __expf(mr0 - mn0);
        const float a1  = __expf(mr1 - mn1);
        float sum0 = 0.f, sum1 = 0.f;
#pragma unroll
        for (int nt = 0; nt < 8; nt++) {
            s[nt][0] = __expf(s[nt][0] - mn0);
            s[nt][1] = __expf(s[nt][1] - mn0);
            s[nt][2] = __expf(s[nt][2] - mn1);
            s[nt][3] = __expf(s[nt][3] - mn1);
            sum0 += s[nt][0] + s[nt][1];
            sum1 += s[nt][2] + s[nt][3];
        }
        sum0 += __shfl_xor_sync(0xffffffffu, sum0, 1);
        sum0 += __shfl_xor_sync(0xffffffffu, sum0, 2);
        sum1 += __shfl_xor_sync(0xffffffffu, sum1, 1);
        sum1 += __shfl_xor_sync(0xffffffffu, sum1, 2);
        lr0 = lr0 * a0 + sum0;  mr0 = mn0;
        lr1 = lr1 * a1 + sum1;  mr1 = mn1;

#pragma unroll
        for (int nt = 0; nt < 8; nt++) {
            o[nt][0] *= a0; o[nt][1] *= a0;
            o[nt][2] *= a1; o[nt][3] *= a1;
        }

        // store P (rna-rounded) to warp's 16-row band of Ps
#pragma unroll
        for (int nt = 0; nt < 8; nt++) {
            *(float2*)&Ps[qr * LDSZ + nt * 8 + 2 * tg] =
                make_float2(rna_tf32(s[nt][0]), rna_tf32(s[nt][1]));
            *(float2*)&Ps[(qr + 8) * LDSZ + nt * 8 + 2 * tg] =
                make_float2(rna_tf32(s[nt][2]), rna_tf32(s[nt][3]));
        }
        __syncwarp();

        // ---- O += P * V  (m=16 queries, n=8 of d, k=8 keys) ----
#pragma unroll
        for (int ks = 0; ks < 8; ks++) {
            uint32_t p[4];
            p[0] = fau(Ps[qr * LDSZ + ks * 8 + tg]);
            p[1] = fau(Ps[(qr + 8) * LDSZ + ks * 8 + tg]);
            p[2] = fau(Ps[qr * LDSZ + ks * 8 + tg + 4]);
            p[3] = fau(Ps[(qr + 8) * LDSZ + ks * 8 + tg + 4]);
#pragma unroll
            for (int nt = 0; nt < 8; nt++) {
                const uint32_t b0 = fau(Vs[(ks * 8 + tg) * LDSZ + nt * 8 + g]);
                const uint32_t b1 = fau(Vs[(ks * 8 + tg + 4) * LDSZ + nt * 8 + g]);
                mma8(o[nt], p, b0, b1);
            }
        }
        __syncthreads();
    }

    // Epilogue: normalize, rna-round (GEMM3 operand), write [n][h*64+d]
    const float inv0 = 1.f / lr0;
    const float inv1 = 1.f / lr1;
    const int row0 = qb * 64 + qr;
#pragma unroll
    for (int nt = 0; nt < 8; nt++) {
        const int col = h * 64 + nt * 8 + 2 * tg;
        *(float2*)&g_O[(size_t)row0 * EMB + col] =
            make_float2(rna_tf32(o[nt][0] * inv0), rna_tf32(o[nt][1] * inv0));
        *(float2*)&g_O[(size_t)(row0 + 8) * EMB + col] =
            make_float2(rna_tf32(o[nt][2] * inv1), rna_tf32(o[nt][3] * inv1));
    }
}

// ============================================================================
// Host launcher
// ============================================================================
extern "C" void kernel_launch(void* const* d_in, const int* in_sizes, int n_in,
                              void* d_out, int out_size)
{
    (void)in_sizes; (void)n_in; (void)out_size;
    const float* x     = (const float*)d_in[0];   // [1,4096,1024]
    const float* qkv_w = (const float*)d_in[1];   // [3072,1024]
    const float* out_w = (const float*)d_in[2];   // [1024,1024]
    const float* out_b = (const float*)d_in[3];   // [1024]
    float* y = (float*)d_out;                     // [1,4096,1024]

    void* pO = nullptr;
    cudaGetSymbolAddress(&pO, g_O);

    cudaFuncSetAttribute(tc_gemm<0>, cudaFuncAttributeMaxDynamicSharedMemorySize, GEMM_SMEM);
    cudaFuncSetAttribute(tc_gemm<1>, cudaFuncAttributeMaxDynamicSharedMemorySize, GEMM_SMEM);
    cudaFuncSetAttribute(attn_kernel, cudaFuncAttributeMaxDynamicSharedMemorySize, ATTN_SMEM);

    // 1) QKV projection -> g_Q (*0.125, tf32) / g_K / g_V
    tc_gemm<0><<<dim3(24, 32), 256, GEMM_SMEM>>>(x, qkv_w, nullptr, nullptr);

    // 2) flash attention (tf32 mma), writes tf32-rounded g_O
    attn_kernel<<<dim3(NTOK / 64, NH), 128, ATTN_SMEM>>>();

    // 3) output projection + bias
    tc_gemm<1><<<dim3(8, 32), 256, GEMM_SMEM>>>((const float*)pO, out_w, out_b, y);
}

// round 9
// speedup vs baseline: 2.9585x; 1.5270x over previous
#include <cuda_runtime.h>
#include <math.h>
#include <stdint.h>

// ============================================================================
// Problem constants
// ============================================================================
#define NTOK 4096
#define NH   16
#define HD   64
#define EMB  1024

// Scratch (__device__ globals; no allocations allowed)
__device__ __align__(128) float g_Q[NH * NTOK * HD];   // [h][n][d], *0.125, tf32-rounded
__device__ __align__(128) float g_K[NH * NTOK * HD];   // tf32-rounded
__device__ __align__(128) float g_V[NH * NTOK * HD];   // tf32-rounded
__device__ __align__(128) float g_O[NTOK * EMB];       // [n][h*64+d], tf32-rounded

// ============================================================================
// Helpers
// ============================================================================
__device__ __forceinline__ float rna_tf32(float x) {
    float y; asm("cvt.rna.tf32.f32 %0, %1;" : "=f"(y) : "f"(x)); return y;
}
__device__ __forceinline__ uint32_t fau(float x) { return __float_as_uint(x); }

// D += A*B, m16n8k8 tf32 (A row-major 16x8, B col-major 8x8, f32 accum)
__device__ __forceinline__ void mma8(float* d, const uint32_t* a, uint32_t b0, uint32_t b1) {
    asm volatile(
        "mma.sync.aligned.m16n8k8.row.col.f32.tf32.tf32.f32 "
        "{%0,%1,%2,%3}, {%4,%5,%6,%7}, {%8,%9}, {%0,%1,%2,%3};"
        : "+f"(d[0]), "+f"(d[1]), "+f"(d[2]), "+f"(d[3])
        : "r"(a[0]), "r"(a[1]), "r"(a[2]), "r"(a[3]), "r"(b0), "r"(b1));
}

// ============================================================================
// tf32 mma.sync GEMM: C[128x128 tile] = A[Mx1024] * B[Nx1024]^T
// 256 threads = 8 warps as 2(m)x4(n); warp tile 64x32; K-tile 32, 2-stage smem.
// Operands rna-rounded to tf32 at SMEM store.
// MODE 0: A=x, B=qkv_w -> scatter rna(Q*0.125)/rna(K)/rna(V)
// MODE 1: A=g_O, B=out_w -> C = y + bias (fp32)
// ============================================================================
#define GPAD 36
#define GEMM_SMEM (4 * 128 * GPAD * (int)sizeof(float))   // 2 stages x (A+B)

template <int MODE>
__global__ void __launch_bounds__(256)
tc_gemm(const float* __restrict__ A, const float* __restrict__ B,
        const float* __restrict__ bias, float* __restrict__ C)
{
    extern __shared__ float gs[];
    float* sA[2] = { gs,                gs + 2 * 128 * GPAD };
    float* sB[2] = { gs + 128 * GPAD,   gs + 3 * 128 * GPAD };

    const int t    = threadIdx.x;
    const int wid  = t >> 5;
    const int lane = t & 31;
    const int g    = lane >> 2;      // group id (0..7)
    const int tg   = lane & 3;       // thread in group
    const int bm   = blockIdx.y, bn = blockIdx.x;
    const int wm   = (wid & 1) * 64;
    const int wn   = (wid >> 1) * 32;

    // global load mapping: warp covers 4 rows x 32 floats, 4 passes
    const int lrow0 = wid * 4 + (lane >> 3);   // 0..31
    const int lcol  = (lane & 7) * 4;          // 0..28

    const float* Ap = A + (size_t)(bm * 128 + lrow0) * 1024 + lcol;
    const float* Bp = B + (size_t)(bn * 128 + lrow0) * 1024 + lcol;

    float d[4][4][4];
#pragma unroll
    for (int mt = 0; mt < 4; mt++)
#pragma unroll
        for (int nt = 0; nt < 4; nt++)
#pragma unroll
            for (int r = 0; r < 4; r++) d[mt][nt][r] = 0.f;

    float4 ra[4], rb[4];
    auto ldg = [&](int kt) {
#pragma unroll
        for (int i = 0; i < 4; i++) {
            ra[i] = *(const float4*)(Ap + (size_t)i * 32 * 1024 + kt * 32);
            rb[i] = *(const float4*)(Bp + (size_t)i * 32 * 1024 + kt * 32);
        }
    };
    auto sts = [&](int st) {
#pragma unroll
        for (int i = 0; i < 4; i++) {
            float4 a = ra[i], b = rb[i];
            a.x = rna_tf32(a.x); a.y = rna_tf32(a.y); a.z = rna_tf32(a.z); a.w = rna_tf32(a.w);
            b.x = rna_tf32(b.x); b.y = rna_tf32(b.y); b.z = rna_tf32(b.z); b.w = rna_tf32(b.w);
            *(float4*)(sA[st] + (lrow0 + i * 32) * GPAD + lcol) = a;
            *(float4*)(sB[st] + (lrow0 + i * 32) * GPAD + lcol) = b;
        }
    };

    ldg(0);
    sts(0);
    __syncthreads();

    for (int kt = 0; kt < 32; kt++) {
        const int cur = kt & 1;
        if (kt + 1 < 32) ldg(kt + 1);

        const float* cA = sA[cur];
        const float* cB = sB[cur];
#pragma unroll
        for (int ks = 0; ks < 4; ks++) {
            uint32_t a[4][4], b[4][2];
#pragma unroll
            for (int mt = 0; mt < 4; mt++) {
                const int r = wm + mt * 16 + g;
                a[mt][0] = fau(cA[r * GPAD + ks * 8 + tg]);
                a[mt][1] = fau(cA[(r + 8) * GPAD + ks * 8 + tg]);
                a[mt][2] = fau(cA[r * GPAD + ks * 8 + tg + 4]);
                a[mt][3] = fau(cA[(r + 8) * GPAD + ks * 8 + tg + 4]);
            }
#pragma unroll
            for (int nt = 0; nt < 4; nt++) {
                const int r = wn + nt * 8 + g;
                b[nt][0] = fau(cB[r * GPAD + ks * 8 + tg]);
                b[nt][1] = fau(cB[r * GPAD + ks * 8 + tg + 4]);
            }
#pragma unroll
            for (int mt = 0; mt < 4; mt++)
#pragma unroll
                for (int nt = 0; nt < 4; nt++)
                    mma8(d[mt][nt], a[mt], b[nt][0], b[nt][1]);
        }
        if (kt + 1 < 32) sts(cur ^ 1);
        __syncthreads();
    }

    // Epilogue. C fragment (m16n8): c0=(g,2tg) c1=(g,2tg+1) c2=(g+8,2tg) c3=(g+8,2tg+1)
    if (MODE == 0) {
        const int part = bn >> 3;                      // 0=Q 1=K 2=V
        const float scale = (part == 0) ? 0.125f : 1.0f;
        float* dst = (part == 0) ? g_Q : ((part == 1) ? g_K : g_V);
#pragma unroll
        for (int mt = 0; mt < 4; mt++) {
            const int row = bm * 128 + wm + mt * 16 + g;
#pragma unroll
            for (int nt = 0; nt < 4; nt++) {
                const int e  = bn * 128 + wn + nt * 8 + 2 * tg;
                const int h  = (e & 1023) >> 6;
                const int d0 = e & 63;
                float2 v0 = make_float2(rna_tf32(d[mt][nt][0] * scale),
                                        rna_tf32(d[mt][nt][1] * scale));
                float2 v1 = make_float2(rna_tf32(d[mt][nt][2] * scale),
                                        rna_tf32(d[mt][nt][3] * scale));
                *(float2*)&dst[((size_t)h * NTOK + row) * HD + d0]     = v0;
                *(float2*)&dst[((size_t)h * NTOK + row + 8) * HD + d0] = v1;
            }
        }
    } else {
#pragma unroll
        for (int mt = 0; mt < 4; mt++) {
            const int row = bm * 128 + wm + mt * 16 + g;
#pragma unroll
            for (int nt = 0; nt < 4; nt++) {
                const int e = bn * 128 + wn + nt * 8 + 2 * tg;
                const float b0 = bias[e], b1 = bias[e + 1];
                float2 v0 = make_float2(d[mt][nt][0] + b0, d[mt][nt][1] + b1);
                float2 v1 = make_float2(d[mt][nt][2] + b0, d[mt][nt][3] + b1);
                *(float2*)&C[(size_t)row * EMB + e]       = v0;
                *(float2*)&C[(size_t)(row + 8) * EMB + e] = v1;
            }
        }
    }
}

// ============================================================================
// Flash attention on tf32 mma.sync. CTA = 64 queries x 1 head, 128 threads
// (4 warps; warp w owns query rows 16w..16w+15). Q fragments held in regs.
// S = Q*K^T and O += P*V via m16n8k8; online softmax on C-fragment registers.
// ============================================================================
#define LDSZ 68
#define ATTN_SMEM (4 * 64 * LDSZ * (int)sizeof(float))

__global__ void __launch_bounds__(128)
attn_kernel()
{
    extern __shared__ float sm[];
    float* Qs = sm;
    float* Ks = sm + 64 * LDSZ;
    float* Vs = sm + 2 * 64 * LDSZ;
    float* Ps = sm + 3 * 64 * LDSZ;

    const int t    = threadIdx.x;
    const int w    = t >> 5;
    const int lane = t & 31;
    const int g    = lane >> 2;
    const int tg   = lane & 3;
    const int qb   = blockIdx.x;
    const int h    = blockIdx.y;
    const int qr   = 16 * w + g;          // query row (lower of pair) in tile

    const float* Qg = g_Q + ((size_t)h * NTOK + qb * 64) * HD;
    const float* Kg = g_K + (size_t)h * NTOK * HD;
    const float* Vg = g_V + (size_t)h * NTOK * HD;

    // Load Q tile
    for (int idx = t; idx < 1024; idx += 128) {
        int r = idx >> 4, c = (idx & 15) << 2;
        *(float4*)(Qs + r * LDSZ + c) = *(const float4*)(Qg + r * 64 + c);
    }
    __syncthreads();

    // Q fragments in registers: q[ks][0..3], ks over d (8 chunks of 8)
    uint32_t q[8][4];
#pragma unroll
    for (int ks = 0; ks < 8; ks++) {
        q[ks][0] = fau(Qs[qr * LDSZ + ks * 8 + tg]);
        q[ks][1] = fau(Qs[(qr + 8) * LDSZ + ks * 8 + tg]);
        q[ks][2] = fau(Qs[qr * LDSZ + ks * 8 + tg + 4]);
        q[ks][3] = fau(Qs[(qr + 8) * LDSZ + ks * 8 + tg + 4]);
    }

    float o[8][4];
#pragma unroll
    for (int nt = 0; nt < 8; nt++)
#pragma unroll
        for (int r = 0; r < 4; r++) o[nt][r] = 0.f;
    float mr0 = -1e30f, mr1 = -1e30f, lr0 = 0.f, lr1 = 0.f;

    for (int kb = 0; kb < NTOK / 64; kb++) {
        const float* Kt = Kg + (size_t)kb * 64 * HD;
        const float* Vt = Vg + (size_t)kb * 64 * HD;
        for (int idx = t; idx < 1024; idx += 128) {
            int r = idx >> 4, c = (idx & 15) << 2;
            *(float4*)(Ks + r * LDSZ + c) = *(const float4*)(Kt + r * 64 + c);
            *(float4*)(Vs + r * LDSZ + c) = *(const float4*)(Vt + r * 64 + c);
        }
        __syncthreads();

        // ---- S = Q * K^T  (m=16 queries, n=8 keys per tile, k=d) ----
        float s[8][4];
#pragma unroll
        for (int nt = 0; nt < 8; nt++)
#pragma unroll
            for (int r = 0; r < 4; r++) s[nt][r] = 0.f;

#pragma unroll
        for (int ks = 0; ks < 8; ks++) {
#pragma unroll
            for (int nt = 0; nt < 8; nt++) {
                const float* kp = Ks + (nt * 8 + g) * LDSZ + ks * 8 + tg;
                mma8(s[nt], q[ks], fau(kp[0]), fau(kp[4]));
            }
        }

        // ---- online softmax (rows qr and qr+8) ----
        float mx0 = -1e30f, mx1 = -1e30f;
#pragma unroll
        for (int nt = 0; nt < 8; nt++) {
            mx0 = fmaxf(mx0, fmaxf(s[nt][0], s[nt][1]));
            mx1 = fmaxf(mx1, fmaxf(s[nt][2], s[nt][3]));
        }
        mx0 = fmaxf(mx0, __shfl_xor_sync(0xffffffffu, mx0, 1));
        mx0 = fmaxf(mx0, __shfl_xor_sync(0xffffffffu, mx0, 2));
        mx1 = fmaxf(mx1, __shfl_xor_sync(0xffffffffu, mx1, 1));
        mx1 = fmaxf(mx1, __shfl_xor_sync(0xffffffffu, mx1, 2));

        const float mn0 = fmaxf(mr0, mx0);
        const float mn1 = fmaxf(mr1, mx1);
        const float a0  = __expf(mr0 - mn0);
        const float a1  = __expf(mr1 - mn1);
        float sum0 = 0.f, sum1 = 0.f;
#pragma unroll
        for (int nt = 0; nt < 8; nt++) {
            s[nt][0] = __expf(s[nt][0] - mn0);
            s[nt][1] = __expf(s[nt][1] - mn0);
            s[nt][2] = __expf(s[nt][2] - mn1);
            s[nt][3] = __expf(s[nt][3] - mn1);
            sum0 += s[nt][0] + s[nt][1];
            sum1 += s[nt][2] + s[nt][3];
        }
        sum0 += __shfl_xor_sync(0xffffffffu, sum0, 1);
        sum0 += __shfl_xor_sync(0xffffffffu, sum0, 2);
        sum1 += __shfl_xor_sync(0xffffffffu, sum1, 1);
        sum1 += __shfl_xor_sync(0xffffffffu, sum1, 2);
        lr0 = lr0 * a0 + sum0;  mr0 = mn0;
        lr1 = lr1 * a1 + sum1;  mr1 = mn1;

#pragma unroll
        for (int nt = 0; nt < 8; nt++) {
            o[nt][0] *= a0; o[nt][1] *= a0;
            o[nt][2] *= a1; o[nt][3] *= a1;
        }

        // store P (rna-rounded) to warp's 16-row band of Ps
#pragma unroll
        for (int nt = 0; nt < 8; nt++) {
            *(float2*)&Ps[qr * LDSZ + nt * 8 + 2 * tg] =
                make_float2(rna_tf32(s[nt][0]), rna_tf32(s[nt][1]));
            *(float2*)&Ps[(qr + 8) * LDSZ + nt * 8 + 2 * tg] =
                make_float2(rna_tf32(s[nt][2]), rna_tf32(s[nt][3]));
        }
        __syncwarp();

        // ---- O += P * V  (m=16 queries, n=8 of d, k=8 keys) ----
#pragma unroll
        for (int ks = 0; ks < 8; ks++) {
            uint32_t p[4];
            p[0] = fau(Ps[qr * LDSZ + ks * 8 + tg]);
            p[1] = fau(Ps[(qr + 8) * LDSZ + ks * 8 + tg]);
            p[2] = fau(Ps[qr * LDSZ + ks * 8 + tg + 4]);
            p[3] = fau(Ps[(qr + 8) * LDSZ + ks * 8 + tg + 4]);
#pragma unroll
            for (int nt = 0; nt < 8; nt++) {
                const uint32_t b0 = fau(Vs[(ks * 8 + tg) * LDSZ + nt * 8 + g]);
                const uint32_t b1 = fau(Vs[(ks * 8 + tg + 4) * LDSZ + nt * 8 + g]);
                mma8(o[nt], p, b0, b1);
            }
        }
        __syncthreads();
    }

    // Epilogue: normalize, rna-round (GEMM3 operand), write [n][h*64+d]
    const float inv0 = 1.f / lr0;
    const float inv1 = 1.f / lr1;
    const int row0 = qb * 64 + qr;
#pragma unroll
    for (int nt = 0; nt < 8; nt++) {
        const int col = h * 64 + nt * 8 + 2 * tg;
        *(float2*)&g_O[(size_t)row0 * EMB + col] =
            make_float2(rna_tf32(o[nt][0] * inv0), rna_tf32(o[nt][1] * inv0));
        *(float2*)&g_O[(size_t)(row0 + 8) * EMB + col] =
            make_float2(rna_tf32(o[nt][2] * inv1), rna_tf32(o[nt][3] * inv1));
    }
}

// ============================================================================
// Host launcher
// ============================================================================
extern "C" void kernel_launch(void* const* d_in, const int* in_sizes, int n_in,
                              void* d_out, int out_size)
{
    (void)in_sizes; (void)n_in; (void)out_size;
    const float* x     = (const float*)d_in[0];   // [1,4096,1024]
    const float* qkv_w = (const float*)d_in[1];   // [3072,1024]
    const float* out_w = (const float*)d_in[2];   // [1024,1024]
    const float* out_b = (const float*)d_in[3];   // [1024]
    float* y = (float*)d_out;                     // [1,4096,1024]

    void* pO = nullptr;
    cudaGetSymbolAddress(&pO, g_O);

    cudaFuncSetAttribute(tc_gemm<0>, cudaFuncAttributeMaxDynamicSharedMemorySize, GEMM_SMEM);
    cudaFuncSetAttribute(tc_gemm<1>, cudaFuncAttributeMaxDynamicSharedMemorySize, GEMM_SMEM);
    cudaFuncSetAttribute(attn_kernel, cudaFuncAttributeMaxDynamicSharedMemorySize, ATTN_SMEM);

    // 1) QKV projection -> g_Q (*0.125, tf32) / g_K / g_V
    tc_gemm<0><<<dim3(24, 32), 256, GEMM_SMEM>>>(x, qkv_w, nullptr, nullptr);

    // 2) flash attention (tf32 mma), writes tf32-rounded g_O
    attn_kernel<<<dim3(NTOK / 64, NH), 128, ATTN_SMEM>>>();

    // 3) output projection + bias
    tc_gemm<1><<<dim3(8, 32), 256, GEMM_SMEM>>>((const float*)pO, out_w, out_b, y);
}

// round 10
// speedup vs baseline: 3.4813x; 1.1767x over previous
#include <cuda_runtime.h>
#include <math.h>
#include <stdint.h>

// ============================================================================
// Problem constants
// ============================================================================
#define NTOK 4096
#define NH   16
#define HD   64
#define EMB  1024

// Scratch (__device__ globals; no allocations allowed)
__device__ __align__(128) float g_Q[NH * NTOK * HD];   // [h][n][d], *0.125*log2e, tf32
__device__ __align__(128) float g_K[NH * NTOK * HD];   // [h][n][d], tf32
__device__ __align__(128) float g_V[NH * HD * NTOK];   // TRANSPOSED [h][d][n], tf32
__device__ __align__(128) float g_O[NTOK * EMB];       // [n][h*64+d], tf32

// ============================================================================
// Helpers
// ============================================================================
__device__ __forceinline__ float rna_tf32(float x) {
    float y; asm("cvt.rna.tf32.f32 %0, %1;" : "=f"(y) : "f"(x)); return y;
}
__device__ __forceinline__ float ex2(float x) {
    float y; asm("ex2.approx.f32 %0, %1;" : "=f"(y) : "f"(x)); return y;
}
__device__ __forceinline__ uint32_t fau(float x) { return __float_as_uint(x); }

// D += A*B, m16n8k8 tf32 (A row-major 16x8, B col-major 8x8, f32 accum)
__device__ __forceinline__ void mma8(float* d, const uint32_t* a, uint32_t b0, uint32_t b1) {
    asm volatile(
        "mma.sync.aligned.m16n8k8.row.col.f32.tf32.tf32.f32 "
        "{%0,%1,%2,%3}, {%4,%5,%6,%7}, {%8,%9}, {%0,%1,%2,%3};"
        : "+f"(d[0]), "+f"(d[1]), "+f"(d[2]), "+f"(d[3])
        : "r"(a[0]), "r"(a[1]), "r"(a[2]), "r"(a[3]), "r"(b0), "r"(b1));
}

// ============================================================================
// tf32 mma.sync GEMM: C[128x128 tile] = A[Mx1024] * B[Nx1024]^T
// 256 threads = 8 warps as 2(m)x4(n); warp tile 64x32; K-tile 32, 2-stage smem.
// MODE 0: A=x, B=qkv_w -> scatter Q(*0.125*log2e)/K/[V transposed], tf32-rounded
// MODE 1: A=g_O, B=out_w -> C = y + bias (fp32)
// ============================================================================
#define GPAD 36
#define GEMM_SMEM (4 * 128 * GPAD * (int)sizeof(float))

#define QSCALE 0.180336879f   // 0.125 * log2(e)

template <int MODE>
__global__ void __launch_bounds__(256)
tc_gemm(const float* __restrict__ A, const float* __restrict__ B,
        const float* __restrict__ bias, float* __restrict__ C)
{
    extern __shared__ float gs[];
    float* sA[2] = { gs,                gs + 2 * 128 * GPAD };
    float* sB[2] = { gs + 128 * GPAD,   gs + 3 * 128 * GPAD };

    const int t    = threadIdx.x;
    const int wid  = t >> 5;
    const int lane = t & 31;
    const int g    = lane >> 2;
    const int tg   = lane & 3;
    const int bm   = blockIdx.y, bn = blockIdx.x;
    const int wm   = (wid & 1) * 64;
    const int wn   = (wid >> 1) * 32;

    const int lrow0 = wid * 4 + (lane >> 3);
    const int lcol  = (lane & 7) * 4;

    const float* Ap = A + (size_t)(bm * 128 + lrow0) * 1024 + lcol;
    const float* Bp = B + (size_t)(bn * 128 + lrow0) * 1024 + lcol;

    float d[4][4][4];
#pragma unroll
    for (int mt = 0; mt < 4; mt++)
#pragma unroll
        for (int nt = 0; nt < 4; nt++)
#pragma unroll
            for (int r = 0; r < 4; r++) d[mt][nt][r] = 0.f;

    float4 ra[4], rb[4];
    auto ldg = [&](int kt) {
#pragma unroll
        for (int i = 0; i < 4; i++) {
            ra[i] = *(const float4*)(Ap + (size_t)i * 32 * 1024 + kt * 32);
            rb[i] = *(const float4*)(Bp + (size_t)i * 32 * 1024 + kt * 32);
        }
    };
    auto sts = [&](int st) {
#pragma unroll
        for (int i = 0; i < 4; i++) {
            float4 a = ra[i], b = rb[i];
            a.x = rna_tf32(a.x); a.y = rna_tf32(a.y); a.z = rna_tf32(a.z); a.w = rna_tf32(a.w);
            b.x = rna_tf32(b.x); b.y = rna_tf32(b.y); b.z = rna_tf32(b.z); b.w = rna_tf32(b.w);
            *(float4*)(sA[st] + (lrow0 + i * 32) * GPAD + lcol) = a;
            *(float4*)(sB[st] + (lrow0 + i * 32) * GPAD + lcol) = b;
        }
    };

    ldg(0);
    sts(0);
    __syncthreads();

    for (int kt = 0; kt < 32; kt++) {
        const int cur = kt & 1;
        if (kt + 1 < 32) ldg(kt + 1);

        const float* cA = sA[cur];
        const float* cB = sB[cur];
#pragma unroll
        for (int ks = 0; ks < 4; ks++) {
            uint32_t a[4][4], b[4][2];
#pragma unroll
            for (int mt = 0; mt < 4; mt++) {
                const int r = wm + mt * 16 + g;
                a[mt][0] = fau(cA[r * GPAD + ks * 8 + tg]);
                a[mt][1] = fau(cA[(r + 8) * GPAD + ks * 8 + tg]);
                a[mt][2] = fau(cA[r * GPAD + ks * 8 + tg + 4]);
                a[mt][3] = fau(cA[(r + 8) * GPAD + ks * 8 + tg + 4]);
            }
#pragma unroll
            for (int nt = 0; nt < 4; nt++) {
                const int r = wn + nt * 8 + g;
                b[nt][0] = fau(cB[r * GPAD + ks * 8 + tg]);
                b[nt][1] = fau(cB[r * GPAD + ks * 8 + tg + 4]);
            }
#pragma unroll
            for (int mt = 0; mt < 4; mt++)
#pragma unroll
                for (int nt = 0; nt < 4; nt++)
                    mma8(d[mt][nt], a[mt], b[nt][0], b[nt][1]);
        }
        if (kt + 1 < 32) sts(cur ^ 1);
        __syncthreads();
    }

    // Epilogue. C fragment (m16n8): c0=(g,2tg) c1=(g,2tg+1) c2=(g+8,2tg) c3=(g+8,2tg+1)
    if (MODE == 0) {
        const int part = bn >> 3;                      // 0=Q 1=K 2=V
#pragma unroll
        for (int mt = 0; mt < 4; mt++) {
            const int row = bm * 128 + wm + mt * 16 + g;
#pragma unroll
            for (int nt = 0; nt < 4; nt++) {
                const int e  = bn * 128 + wn + nt * 8 + 2 * tg;
                const int h  = (e & 1023) >> 6;
                const int d0 = e & 63;
                if (part == 2) {
                    // transposed V: g_V[(h*64+d)*NTOK + n]
                    float* b0 = g_V + ((size_t)(h * HD + d0)) * NTOK;
                    float* b1 = b0 + NTOK;
                    b0[row]     = rna_tf32(d[mt][nt][0]);
                    b1[row]     = rna_tf32(d[mt][nt][1]);
                    b0[row + 8] = rna_tf32(d[mt][nt][2]);
                    b1[row + 8] = rna_tf32(d[mt][nt][3]);
                } else {
                    const float scale = (part == 0) ? QSCALE : 1.0f;
                    float* dst = (part == 0) ? g_Q : g_K;
                    float2 v0 = make_float2(rna_tf32(d[mt][nt][0] * scale),
                                            rna_tf32(d[mt][nt][1] * scale));
                    float2 v1 = make_float2(rna_tf32(d[mt][nt][2] * scale),
                                            rna_tf32(d[mt][nt][3] * scale));
                    *(float2*)&dst[((size_t)h * NTOK + row) * HD + d0]     = v0;
                    *(float2*)&dst[((size_t)h * NTOK + row + 8) * HD + d0] = v1;
                }
            }
        }
    } else {
#pragma unroll
        for (int mt = 0; mt < 4; mt++) {
            const int row = bm * 128 + wm + mt * 16 + g;
#pragma unroll
            for (int nt = 0; nt < 4; nt++) {
                const int e = bn * 128 + wn + nt * 8 + 2 * tg;
                const float b0 = bias[e], b1 = bias[e + 1];
                float2 v0 = make_float2(d[mt][nt][0] + b0, d[mt][nt][1] + b1);
                float2 v1 = make_float2(d[mt][nt][2] + b0, d[mt][nt][3] + b1);
                *(float2*)&C[(size_t)row * EMB + e]       = v0;
                *(float2*)&C[(size_t)(row + 8) * EMB + e] = v1;
            }
        }
    }
}

// ============================================================================
// Flash attention, tf32 mma.sync, m=32 per warp.
// CTA = 128 queries x 1 head, 128 threads (4 warps; warp w owns rows 32w..32w+31,
// two 16-row fragment groups u=0,1). K/V B-fragments loaded once per (ks,nt),
// shared by both groups. V is pre-transposed [d][n] -> conflict-free B loads.
// Softmax in exp2 domain (Q pre-scaled by 0.125*log2e).
// ============================================================================
#define LDK 68
#define ATTN_SMEM ((64 * LDK + 64 * LDK + 128 * LDK) * (int)sizeof(float))

__global__ void __launch_bounds__(128)
attn_kernel()
{
    extern __shared__ float sm[];
    float* Ks  = sm;                  // [64 keys][LDK]  (K[key][d])
    float* Vts = sm + 64 * LDK;       // [64 d][LDK]     (V^T[d][key])
    float* Ps  = sm + 2 * 64 * LDK;   // [128 q][LDK]    (P, also Q staging)

    const int t    = threadIdx.x;
    const int w    = t >> 5;
    const int lane = t & 31;
    const int g    = lane >> 2;
    const int tg   = lane & 3;
    const int qb   = blockIdx.x;      // 0..31 (128-query blocks)
    const int h    = blockIdx.y;

    const float* Qg = g_Q + ((size_t)h * NTOK + qb * 128) * HD;
    const float* Kg = g_K + (size_t)h * NTOK * HD;
    const float* Vg = g_V + (size_t)h * HD * NTOK;   // row d: [NTOK] keys

    // ---- stage Q tile (128x64) into Ps, pull fragments into registers ----
    for (int idx = t; idx < 2048; idx += 128) {
        int r = idx >> 4, c = (idx & 15) << 2;
        *(float4*)(Ps + r * LDK + c) = *(const float4*)(Qg + r * 64 + c);
    }
    __syncthreads();

    uint32_t q[2][8][4];
#pragma unroll
    for (int u = 0; u < 2; u++) {
        const int r0 = 32 * w + 16 * u + g;
#pragma unroll
        for (int ks = 0; ks < 8; ks++) {
            q[u][ks][0] = fau(Ps[r0 * LDK + ks * 8 + tg]);
            q[u][ks][1] = fau(Ps[(r0 + 8) * LDK + ks * 8 + tg]);
            q[u][ks][2] = fau(Ps[r0 * LDK + ks * 8 + tg + 4]);
            q[u][ks][3] = fau(Ps[(r0 + 8) * LDK + ks * 8 + tg + 4]);
        }
    }
    __syncthreads();

    float o[2][8][4];
    float mr[2][2], lr[2][2];
#pragma unroll
    for (int u = 0; u < 2; u++) {
        mr[u][0] = mr[u][1] = -1e30f;
        lr[u][0] = lr[u][1] = 0.f;
#pragma unroll
        for (int nt = 0; nt < 8; nt++)
#pragma unroll
            for (int r = 0; r < 4; r++) o[u][nt][r] = 0.f;
    }

    for (int kb = 0; kb < NTOK / 64; kb++) {
        // load K tile [64 keys][64 d] and V^T tile [64 d][64 keys]
        for (int idx = t; idx < 1024; idx += 128) {
            int r = idx >> 4, c = (idx & 15) << 2;
            *(float4*)(Ks  + r * LDK + c) = *(const float4*)(Kg + (size_t)(kb * 64 + r) * 64 + c);
            *(float4*)(Vts + r * LDK + c) = *(const float4*)(Vg + (size_t)r * NTOK + kb * 64 + c);
        }
        __syncthreads();

        // ---- S = Q * K^T ----
        float s[2][8][4];
#pragma unroll
        for (int u = 0; u < 2; u++)
#pragma unroll
            for (int nt = 0; nt < 8; nt++)
#pragma unroll
                for (int r = 0; r < 4; r++) s[u][nt][r] = 0.f;

#pragma unroll
        for (int ks = 0; ks < 8; ks++) {
#pragma unroll
            for (int nt = 0; nt < 8; nt++) {
                const float* kp = Ks + (nt * 8 + g) * LDK + ks * 8 + tg;
                const uint32_t b0 = fau(kp[0]);
                const uint32_t b1 = fau(kp[4]);
                mma8(s[0][nt], q[0][ks], b0, b1);
                mma8(s[1][nt], q[1][ks], b0, b1);
            }
        }

        // ---- online softmax (exp2 domain), P store ----
#pragma unroll
        for (int u = 0; u < 2; u++) {
            const int r0 = 32 * w + 16 * u + g;
            float mx0 = -1e30f, mx1 = -1e30f;
#pragma unroll
            for (int nt = 0; nt < 8; nt++) {
                mx0 = fmaxf(mx0, fmaxf(s[u][nt][0], s[u][nt][1]));
                mx1 = fmaxf(mx1, fmaxf(s[u][nt][2], s[u][nt][3]));
            }
            mx0 = fmaxf(mx0, __shfl_xor_sync(0xffffffffu, mx0, 1));
            mx0 = fmaxf(mx0, __shfl_xor_sync(0xffffffffu, mx0, 2));
            mx1 = fmaxf(mx1, __shfl_xor_sync(0xffffffffu, mx1, 1));
            mx1 = fmaxf(mx1, __shfl_xor_sync(0xffffffffu, mx1, 2));

            const float mn0 = fmaxf(mr[u][0], mx0);
            const float mn1 = fmaxf(mr[u][1], mx1);
            const float a0  = ex2(mr[u][0] - mn0);
            const float a1  = ex2(mr[u][1] - mn1);
            float sum0 = 0.f, sum1 = 0.f;
#pragma unroll
            for (int nt = 0; nt < 8; nt++) {
                s[u][nt][0] = ex2(s[u][nt][0] - mn0);
                s[u][nt][1] = ex2(s[u][nt][1] - mn0);
                s[u][nt][2] = ex2(s[u][nt][2] - mn1);
                s[u][nt][3] = ex2(s[u][nt][3] - mn1);
                sum0 += s[u][nt][0] + s[u][nt][1];
                sum1 += s[u][nt][2] + s[u][nt][3];
            }
            sum0 += __shfl_xor_sync(0xffffffffu, sum0, 1);
            sum0 += __shfl_xor_sync(0xffffffffu, sum0, 2);
            sum1 += __shfl_xor_sync(0xffffffffu, sum1, 1);
            sum1 += __shfl_xor_sync(0xffffffffu, sum1, 2);
            lr[u][0] = lr[u][0] * a0 + sum0;  mr[u][0] = mn0;
            lr[u][1] = lr[u][1] * a1 + sum1;  mr[u][1] = mn1;

#pragma unroll
            for (int nt = 0; nt < 8; nt++) {
                o[u][nt][0] *= a0; o[u][nt][1] *= a0;
                o[u][nt][2] *= a1; o[u][nt][3] *= a1;
                *(float2*)&Ps[r0 * LDK + nt * 8 + 2 * tg] =
                    make_float2(rna_tf32(s[u][nt][0]), rna_tf32(s[u][nt][1]));
                *(float2*)&Ps[(r0 + 8) * LDK + nt * 8 + 2 * tg] =
                    make_float2(rna_tf32(s[u][nt][2]), rna_tf32(s[u][nt][3]));
            }
        }
        __syncwarp();   // P rows are warp-private

        // ---- O += P * V  (B-fragments from V^T: conflict-free) ----
#pragma unroll
        for (int ks = 0; ks < 8; ks++) {
            uint32_t p0[4], p1[4];
            const int ra = 32 * w + g;
            p0[0] = fau(Ps[ra * LDK + ks * 8 + tg]);
            p0[1] = fau(Ps[(ra + 8) * LDK + ks * 8 + tg]);
            p0[2] = fau(Ps[ra * LDK + ks * 8 + tg + 4]);
            p0[3] = fau(Ps[(ra + 8) * LDK + ks * 8 + tg + 4]);
            p1[0] = fau(Ps[(ra + 16) * LDK + ks * 8 + tg]);
            p1[1] = fau(Ps[(ra + 24) * LDK + ks * 8 + tg]);
            p1[2] = fau(Ps[(ra + 16) * LDK + ks * 8 + tg + 4]);
            p1[3] = fau(Ps[(ra + 24) * LDK + ks * 8 + tg + 4]);
#pragma unroll
            for (int nt = 0; nt < 8; nt++) {
                const float* vp = Vts + (nt * 8 + g) * LDK + ks * 8 + tg;
                const uint32_t b0 = fau(vp[0]);
                const uint32_t b1 = fau(vp[4]);
                mma8(o[0][nt], p0, b0, b1);
                mma8(o[1][nt], p1, b0, b1);
            }
        }
        __syncthreads();   // Ks/Vts consumed before next tile load
    }

    // ---- epilogue: normalize, tf32-round (GEMM3 operand), write [n][h*64+d] ----
#pragma unroll
    for (int u = 0; u < 2; u++) {
        const float inv0 = 1.f / lr[u][0];
        const float inv1 = 1.f / lr[u][1];
        const int row0 = qb * 128 + 32 * w + 16 * u + g;
#pragma unroll
        for (int nt = 0; nt < 8; nt++) {
            const int col = h * 64 + nt * 8 + 2 * tg;
            *(float2*)&g_O[(size_t)row0 * EMB + col] =
                make_float2(rna_tf32(o[u][nt][0] * inv0), rna_tf32(o[u][nt][1] * inv0));
            *(float2*)&g_O[(size_t)(row0 + 8) * EMB + col] =
                make_float2(rna_tf32(o[u][nt][2] * inv1), rna_tf32(o[u][nt][3] * inv1));
        }
    }
}

// ============================================================================
// Host launcher
// ============================================================================
extern "C" void kernel_launch(void* const* d_in, const int* in_sizes, int n_in,
                              void* d_out, int out_size)
{
    (void)in_sizes; (void)n_in; (void)out_size;
    const float* x     = (const float*)d_in[0];   // [1,4096,1024]
    const float* qkv_w = (const float*)d_in[1];   // [3072,1024]
    const float* out_w = (const float*)d_in[2];   // [1024,1024]
    const float* out_b = (const float*)d_in[3];   // [1024]
    float* y = (float*)d_out;                     // [1,4096,1024]

    void* pO = nullptr;
    cudaGetSymbolAddress(&pO, g_O);

    cudaFuncSetAttribute(tc_gemm<0>, cudaFuncAttributeMaxDynamicSharedMemorySize, GEMM_SMEM);
    cudaFuncSetAttribute(tc_gemm<1>, cudaFuncAttributeMaxDynamicSharedMemorySize, GEMM_SMEM);
    cudaFuncSetAttribute(attn_kernel, cudaFuncAttributeMaxDynamicSharedMemorySize, ATTN_SMEM);

    // 1) QKV projection -> g_Q (*0.125*log2e) / g_K / g_V (transposed), all tf32
    tc_gemm<0><<<dim3(24, 32), 256, GEMM_SMEM>>>(x, qkv_w, nullptr, nullptr);

    // 2) flash attention (tf32 mma, m32/warp, exp2 softmax)
    attn_kernel<<<dim3(NTOK / 128, NH), 128, ATTN_SMEM>>>();

    // 3) output projection + bias
    tc_gemm<1><<<dim3(8, 32), 256, GEMM_SMEM>>>((const float*)pO, out_w, out_b, y);
}